// round 16
// baseline (speedup 1.0000x reference)
#include <cuda_runtime.h>
#include <cuda_fp16.h>
#include <math.h>
#include <stdint.h>
#include <string.h>

#define S_B   4
#define S_S   4096
#define S_D   512
#define S_H   8
#define S_DH  64
#define QKV_N (3 * S_D)          /* 1536 */
#define MROWS (S_B * S_S)        /* 16384 */

// Scratch (allocation-free: static device globals), all fp16
__device__ __half g_xh [(size_t)MROWS * S_D];
__device__ __half g_wih[(size_t)QKV_N * S_D];
__device__ __half g_woh[(size_t)S_D * S_D];
__device__ __half g_qkv[(size_t)MROWS * QKV_N];
__device__ __half g_vt [(size_t)S_B * S_H * S_DH * S_S];
__device__ __half g_att[(size_t)MROWS * S_D];

// ---------------------------------------------------------------------------
// helpers
// ---------------------------------------------------------------------------
__device__ __forceinline__ uint32_t h2_as_u32(__half2 h)
{
    uint32_t u;
    memcpy(&u, &h, 4);
    return u;
}
__device__ __forceinline__ __half2 u32_as_h2(uint32_t u)
{
    __half2 h;
    memcpy(&h, &u, 4);
    return h;
}
__device__ __forceinline__ uint32_t ex2_h2(uint32_t x)
{
    uint32_t r;
    asm("ex2.approx.f16x2 %0, %1;" : "=r"(r) : "r"(x));
    return r;
}

// ldmatrix: four 8x8 b16 matrices
__device__ __forceinline__ void ldsm_x4(uint32_t addr, uint32_t* r)
{
    asm volatile("ldmatrix.sync.aligned.m8n8.x4.shared.b16 {%0,%1,%2,%3}, [%4];"
                 : "=r"(r[0]), "=r"(r[1]), "=r"(r[2]), "=r"(r[3]) : "r"(addr));
}

// mma.m16n8k16 fp16, fp32 accumulate
__device__ __forceinline__ void mma_f16(float* d, const uint32_t* a,
                                        uint32_t b0, uint32_t b1)
{
    asm volatile(
        "mma.sync.aligned.m16n8k16.row.col.f32.f16.f16.f32 "
        "{%0,%1,%2,%3}, {%4,%5,%6,%7}, {%8,%9}, {%0,%1,%2,%3};\n"
        : "+f"(d[0]), "+f"(d[1]), "+f"(d[2]), "+f"(d[3])
        : "r"(a[0]), "r"(a[1]), "r"(a[2]), "r"(a[3]), "r"(b0), "r"(b1));
}
// mma.m16n8k16 fp16, fp16 accumulate (D = 2 x f16x2; layout == PV A-frag)
__device__ __forceinline__ void mma_f16acc(uint32_t* d, const uint32_t* a,
                                           uint32_t b0, uint32_t b1)
{
    asm volatile(
        "mma.sync.aligned.m16n8k16.row.col.f16.f16.f16.f16 "
        "{%0,%1}, {%2,%3,%4,%5}, {%6,%7}, {%0,%1};\n"
        : "+r"(d[0]), "+r"(d[1])
        : "r"(a[0]), "r"(a[1]), "r"(a[2]), "r"(a[3]), "r"(b0), "r"(b1));
}

__device__ __forceinline__ void cp_async16(uint32_t saddr, const void* gptr)
{
    asm volatile("cp.async.cg.shared.global [%0], [%1], 16;\n"
                 :: "r"(saddr), "l"(gptr));
}

// ---------------------------------------------------------------------------
// fp32 -> fp16 conversion (n multiple of 4)
// ---------------------------------------------------------------------------
__global__ __launch_bounds__(256) void cvt_f2h(
    const float* __restrict__ in, __half* __restrict__ out, int n)
{
    int i = (blockIdx.x * 256 + threadIdx.x) * 4;
    if (i < n) {
        float4 v = *(const float4*)(in + i);
        *(__half2*)(out + i)     = __floats2half2_rn(v.x, v.y);
        *(__half2*)(out + i + 2) = __floats2half2_rn(v.z, v.w);
    }
}

// ---------------------------------------------------------------------------
// fp16 GEMM:  C[M,N] = A[M,K] @ B[N,K]^T + bias[N]
// 128x128 tile, 256 threads, 3-stage cp.async ring, single barrier/chunk,
// BK=64. (unchanged measured-best)
// ---------------------------------------------------------------------------
#define GLD 72                                      /* smem stride in halves */
#define GSTG 3
#define GSTAGE_H (128 * GLD)                        /* per-operand stage, halves */
#define GEMM_SMEM (GSTG * 2 * GSTAGE_H * 2)         /* 110592 bytes */

template<bool OUT_HALF>
__global__ __launch_bounds__(256, 2) void gemm_h(
    const __half* __restrict__ A, const __half* __restrict__ Bw,
    const float* __restrict__ bias, void* __restrict__ Cout,
    int M, int N, int K)
{
    extern __shared__ char smraw[];
    __half* As = (__half*)smraw;                 // [3][128*GLD]
    __half* Bs = As + GSTG * GSTAGE_H;

    const int t    = threadIdx.x;
    const int warp = t >> 5;
    const int lane = t & 31;
    const int g    = lane >> 2;
    const int tg   = lane & 3;
    const int wm   = (warp >> 1) * 32;
    const int wn   = (warp & 1) * 64;

    const int a_row = lane & 15;
    const int a_col = (lane >> 4) * 8;
    const int b_row = (lane & 7) + ((lane >> 4) << 3);
    const int b_col = ((lane >> 3) & 1) * 8;

    const int m0 = blockIdx.y * 128;
    const int n0 = blockIdx.x * 128;

    uint32_t sA = (uint32_t)__cvta_generic_to_shared(As);
    uint32_t sB = (uint32_t)__cvta_generic_to_shared(Bs);

    // staging: 1024 16B-units per operand per chunk; 4 units/thread
    uint32_t soff[4];
    size_t   goffA[4], goffB[4];
    #pragma unroll
    for (int i = 0; i < 4; i++) {
        int u   = t + i * 256;
        int row = u >> 3;
        int seg = u & 7;
        soff[i]  = (uint32_t)(row * GLD + seg * 8) * 2;
        goffA[i] = (size_t)(m0 + row) * K + seg * 8;
        goffB[i] = (size_t)(n0 + row) * K + seg * 8;
    }

    const int nk = K / 64;

    auto issue = [&](int k, int s) {
        uint32_t off = (uint32_t)(s * GSTAGE_H) * 2;
        #pragma unroll
        for (int i = 0; i < 4; i++) {
            cp_async16(sA + off + soff[i], A  + goffA[i] + k * 64);
            cp_async16(sB + off + soff[i], Bw + goffB[i] + k * 64);
        }
        asm volatile("cp.async.commit_group;\n");
    };

    issue(0, 0);
    issue(1, 1);

    float acc[2][8][4];
    #pragma unroll
    for (int mf = 0; mf < 2; mf++)
        #pragma unroll
        for (int nf = 0; nf < 8; nf++)
            #pragma unroll
            for (int c = 0; c < 4; c++) acc[mf][nf][c] = 0.f;

    int s_cur = 0;
    int s_pre = 2;

    for (int kc = 0; kc < nk; kc++) {
        if (kc + 1 < nk) {
            asm volatile("cp.async.wait_group 1;\n");
        } else {
            asm volatile("cp.async.wait_group 0;\n");
        }
        __syncthreads();   // data ready + stage s_pre provably drained

        if (kc + 2 < nk)
            issue(kc + 2, s_pre);

        const uint32_t aA = sA + (uint32_t)(s_cur * GSTAGE_H) * 2;
        const uint32_t aB = sB + (uint32_t)(s_cur * GSTAGE_H) * 2;

        #pragma unroll
        for (int kf = 0; kf < 4; kf++) {
            const int kk0 = kf * 16;

            uint32_t af[2][4];
            #pragma unroll
            for (int mf = 0; mf < 2; mf++)
                ldsm_x4(aA + (uint32_t)((wm + mf * 16 + a_row) * GLD + kk0 + a_col) * 2,
                        af[mf]);

            #pragma unroll
            for (int np = 0; np < 4; np++) {
                uint32_t bf[4];
                ldsm_x4(aB + (uint32_t)((wn + np * 16 + b_row) * GLD + kk0 + b_col) * 2,
                        bf);
                mma_f16(acc[0][2 * np],     af[0], bf[0], bf[1]);
                mma_f16(acc[1][2 * np],     af[1], bf[0], bf[1]);
                mma_f16(acc[0][2 * np + 1], af[0], bf[2], bf[3]);
                mma_f16(acc[1][2 * np + 1], af[1], bf[2], bf[3]);
            }
        }

        s_cur = (s_cur == 2) ? 0 : s_cur + 1;
        s_pre = (s_pre == 2) ? 0 : s_pre + 1;
    }

    #pragma unroll
    for (int nf = 0; nf < 8; nf++) {
        int col = n0 + wn + nf * 8 + 2 * tg;
        float2 bb = *(const float2*)(bias + col);
        #pragma unroll
        for (int mf = 0; mf < 2; mf++) {
            int row = m0 + wm + mf * 16 + g;
            if (OUT_HALF) {
                __half* C = (__half*)Cout;
                *(__half2*)(C + (size_t)row * N + col) =
                    __floats2half2_rn(acc[mf][nf][0] + bb.x, acc[mf][nf][1] + bb.y);
                *(__half2*)(C + (size_t)(row + 8) * N + col) =
                    __floats2half2_rn(acc[mf][nf][2] + bb.x, acc[mf][nf][3] + bb.y);
            } else {
                float* C = (float*)Cout;
                *(float2*)(C + (size_t)row * N + col) =
                    make_float2(acc[mf][nf][0] + bb.x, acc[mf][nf][1] + bb.y);
                *(float2*)(C + (size_t)(row + 8) * N + col) =
                    make_float2(acc[mf][nf][2] + bb.x, acc[mf][nf][3] + bb.y);
            }
        }
    }
}

// ---------------------------------------------------------------------------
// V transpose (fp16): qkv V section [b][s][h*64+d] -> g_vt [bh][d][s]
// ---------------------------------------------------------------------------
__global__ __launch_bounds__(256) void transpose_v_h(
    const __half* __restrict__ qkv, __half* __restrict__ vt)
{
    __shared__ __half tile[32][34];
    const int bh = blockIdx.z;
    const int b  = bh >> 3;
    const int h  = bh & 7;
    const int d0 = blockIdx.y * 32;
    const int s0 = blockIdx.x * 32;
    const int tx = threadIdx.x;
    const int ty = threadIdx.y;

    const __half* src = qkv + (size_t)(b * S_S) * QKV_N + 2 * S_D + h * S_DH;
    #pragma unroll
    for (int i = 0; i < 4; i++)
        tile[ty + i * 8][tx] = src[(size_t)(s0 + ty + i * 8) * QKV_N + d0 + tx];
    __syncthreads();

    __half* dst = vt + (size_t)bh * S_DH * S_S;
    #pragma unroll
    for (int i = 0; i < 4; i++)
        dst[(size_t)(d0 + ty + i * 8) * S_S + s0 + tx] = tile[tx][ty + i * 8];
}

// ---------------------------------------------------------------------------
// Flash attention: fp16 mma; R15: softmax scale folded into Q at staging
// (Q *= 0.125*log2(e)) and S accumulated in fp16 — the f16x2 accumulator
// layout IS the PV A-fragment, so softmax = ex2.f16x2 directly on the
// accumulator registers (no pack, no scale mul). V path unchanged from the
// measured-best R12/R14 form (pre-transposed g_vt, straight ldmatrix).
// ---------------------------------------------------------------------------
#define LDQ  72
#define LDKs 72
#define LDVt 136
#define K_STAGE_H (128 * LDKs)            /* 9216 halves */
#define V_STAGE_H (64 * LDVt)             /* 8704 halves */
#define STAGE_H   (K_STAGE_H + V_STAGE_H) /* 17920 halves = 35840 B */
#define ATT_SMEM  (2 * STAGE_H * 2)       /* 71680 B */

__device__ __forceinline__ void attn_issue_stage(
    uint32_t sbase, int stage, const __half* kb, const __half* vb,
    int kt, int t)
{
    uint32_t kdst = sbase + (uint32_t)(stage * STAGE_H) * 2;
    uint32_t vdst = kdst + (uint32_t)K_STAGE_H * 2;
    #pragma unroll
    for (int u = t; u < 1024; u += 128) {          // K: 128 keys x 64 dims
        int row = u >> 3, sg = u & 7;
        cp_async16(kdst + (uint32_t)(row * LDKs + sg * 8) * 2,
                   kb + (size_t)(kt + row) * QKV_N + sg * 8);
    }
    #pragma unroll
    for (int u = t; u < 1024; u += 128) {          // V^T: 64 dims x 128 keys
        int d = u >> 4, sg = u & 15;
        cp_async16(vdst + (uint32_t)(d * LDVt + sg * 8) * 2,
                   vb + (size_t)d * S_S + kt + sg * 8);
    }
}

__global__ __launch_bounds__(128) void attn_h(
    const __half* __restrict__ qkv, const __half* __restrict__ vt,
    __half* __restrict__ att)
{
    extern __shared__ char smraw[];
    __half* sm = (__half*)smraw;
    const uint32_t sbase = (uint32_t)__cvta_generic_to_shared(sm);

    const int t    = threadIdx.x;
    const int warp = t >> 5;
    const int lane = t & 31;
    const int g    = lane >> 2;
    const int tg   = lane & 3;

    const int a_row = lane & 15;
    const int a_col = (lane >> 4) * 8;
    const int b_row = (lane & 7) + ((lane >> 4) << 3);
    const int b_col = ((lane >> 3) & 1) * 8;

    const int bh = blockIdx.y;
    const int b  = bh >> 3;
    const int h  = bh & 7;
    const int q0 = blockIdx.x * 128;

    const __half* kb = qkv + (size_t)b * S_S * QKV_N + S_D + h * S_DH;
    const __half* vb = vt + (size_t)bh * S_DH * S_S;

    // ---- prologue: prefetch tile 0 into stage 0 ----
    attn_issue_stage(sbase, 0, kb, vb, 0, t);
    asm volatile("cp.async.commit_group;\n");

    // 0.125 (1/sqrt(dh)) * log2(e): fold into Q so S is already in log2 units
    const __half2 SCQ = __floats2half2_rn(0.18033688f, 0.18033688f);

    // ---- stage Q (pre-scaled) into stage-1 K region ----
    __half* Qs = sm + STAGE_H;
    const uint32_t qaddr = sbase + (uint32_t)STAGE_H * 2;
    const __half* qb = qkv + (size_t)(b * S_S + q0) * QKV_N + h * S_DH;
    #pragma unroll
    for (int u = t; u < 1024; u += 128) {
        int row = u >> 3, sg = u & 7;
        float4 raw = *(const float4*)(qb + (size_t)row * QKV_N + sg * 8);
        __half2* p = (__half2*)&raw;
        p[0] = __hmul2(p[0], SCQ);
        p[1] = __hmul2(p[1], SCQ);
        p[2] = __hmul2(p[2], SCQ);
        p[3] = __hmul2(p[3], SCQ);
        *(float4*)(Qs + row * LDQ + sg * 8) = raw;
    }
    __syncthreads();

    // ---- Q A-fragments via ldmatrix, held for the whole KV loop ----
    uint32_t qa[4][2][4];
    #pragma unroll
    for (int kf = 0; kf < 4; kf++)
        #pragma unroll
        for (int mf = 0; mf < 2; mf++)
            ldsm_x4(qaddr + (uint32_t)((warp * 32 + mf * 16 + a_row) * LDQ
                                       + kf * 16 + a_col) * 2,
                    qa[kf][mf]);
    __syncthreads();   // all warps done reading Q before stage 1 is overwritten

    float of[8][2][4];
    #pragma unroll
    for (int nf = 0; nf < 8; nf++)
        #pragma unroll
        for (int mf = 0; mf < 2; mf++)
            #pragma unroll
            for (int c = 0; c < 4; c++) of[nf][mf][c] = 0.f;

    float lsl[2] = {0.f, 0.f};
    float lsh[2] = {0.f, 0.f};

    const int NT = S_S / 128;    // 32 tiles

    for (int it = 0; it < NT; it++) {
        asm volatile("cp.async.wait_group 0;\n");
        __syncthreads();   // data ready + opposite stage provably drained

        if (it + 1 < NT) {
            attn_issue_stage(sbase, (it + 1) & 1, kb, vb, (it + 1) * 128, t);
            asm volatile("cp.async.commit_group;\n");
        }

        const uint32_t kaddr = sbase + (uint32_t)((it & 1) * STAGE_H) * 2;
        const uint32_t vaddr = kaddr + (uint32_t)K_STAGE_H * 2;

        #pragma unroll
        for (int c = 0; c < 8; c++) {            // 8 chunks of 16 keys
            // ---- S chunk, fp16 accumulate: sfh[nf][mf][2 regs] ----
            uint32_t sfh[2][2][2];
            #pragma unroll
            for (int nf = 0; nf < 2; nf++)
                #pragma unroll
                for (int mf = 0; mf < 2; mf++)
                    sfh[nf][mf][0] = sfh[nf][mf][1] = 0u;

            #pragma unroll
            for (int kf = 0; kf < 4; kf++) {
                uint32_t kb4[4];
                ldsm_x4(kaddr + (uint32_t)((16 * c + b_row) * LDKs
                                           + kf * 16 + b_col) * 2, kb4);
                mma_f16acc(sfh[0][0], qa[kf][0], kb4[0], kb4[1]);
                mma_f16acc(sfh[0][1], qa[kf][1], kb4[0], kb4[1]);
                mma_f16acc(sfh[1][0], qa[kf][0], kb4[2], kb4[3]);
                mma_f16acc(sfh[1][1], qa[kf][1], kb4[2], kb4[3]);
            }

            // ---- softmax: ex2.f16x2 directly on accumulators (scale in Q) ----
            uint32_t pa[2][4];
            #pragma unroll
            for (int mf = 0; mf < 2; mf++) {
                pa[mf][0] = ex2_h2(sfh[0][mf][0]);   // rows g,   keys lo
                pa[mf][1] = ex2_h2(sfh[0][mf][1]);   // rows g+8, keys lo
                pa[mf][2] = ex2_h2(sfh[1][mf][0]);   // rows g,   keys hi
                pa[mf][3] = ex2_h2(sfh[1][mf][1]);   // rows g+8, keys hi
                __half2 sl = __hadd2(u32_as_h2(pa[mf][0]), u32_as_h2(pa[mf][2]));
                __half2 sh = __hadd2(u32_as_h2(pa[mf][1]), u32_as_h2(pa[mf][3]));
                lsl[mf] += __low2float(sl) + __high2float(sl);
                lsh[mf] += __low2float(sh) + __high2float(sh);
            }

            // ---- O += P @ V (keys 16c..16c+15) ----
            #pragma unroll
            for (int np = 0; np < 4; np++) {
                uint32_t v4[4];
                ldsm_x4(vaddr + (uint32_t)((np * 16 + b_row) * LDVt
                                           + 16 * c + b_col) * 2, v4);
                mma_f16(of[2 * np][0],     pa[0], v4[0], v4[1]);
                mma_f16(of[2 * np][1],     pa[1], v4[0], v4[1]);
                mma_f16(of[2 * np + 1][0], pa[0], v4[2], v4[3]);
                mma_f16(of[2 * np + 1][1], pa[1], v4[2], v4[3]);
            }
        }
        // no trailing __syncthreads: next iteration's barrier protects reuse
    }

    // ---- epilogue ----
    #pragma unroll
    for (int mf = 0; mf < 2; mf++) {
        float a = lsl[mf], bsum = lsh[mf];
        a += __shfl_xor_sync(0xffffffffu, a, 1);
        a += __shfl_xor_sync(0xffffffffu, a, 2);
        bsum += __shfl_xor_sync(0xffffffffu, bsum, 1);
        bsum += __shfl_xor_sync(0xffffffffu, bsum, 2);
        float il = 1.f / a;
        float ih = 1.f / bsum;

        int row = q0 + warp * 32 + mf * 16 + g;
        __half* o0 = att + (size_t)(b * S_S + row) * S_D + h * S_DH;
        __half* o1 = o0 + 8 * S_D;
        #pragma unroll
        for (int nf = 0; nf < 8; nf++) {
            int col = nf * 8 + 2 * tg;
            *(__half2*)(o0 + col) =
                __floats2half2_rn(of[nf][mf][0] * il, of[nf][mf][1] * il);
            *(__half2*)(o1 + col) =
                __floats2half2_rn(of[nf][mf][2] * ih, of[nf][mf][3] * ih);
        }
    }
}

// ---------------------------------------------------------------------------
extern "C" void kernel_launch(void* const* d_in, const int* in_sizes, int n_in,
                              void* d_out, int out_size)
{
    (void)in_sizes; (void)n_in; (void)out_size;
    const float* x     = (const float*)d_in[0];
    const float* w_in  = (const float*)d_in[1];
    const float* b_in  = (const float*)d_in[2];
    const float* w_out = (const float*)d_in[3];
    const float* b_out = (const float*)d_in[4];
    float* outp = (float*)d_out;

    __half *xh, *wih, *woh, *qkvp, *vtp, *attp;
    cudaGetSymbolAddress((void**)&xh,  g_xh);
    cudaGetSymbolAddress((void**)&wih, g_wih);
    cudaGetSymbolAddress((void**)&woh, g_woh);
    cudaGetSymbolAddress((void**)&qkvp, g_qkv);
    cudaGetSymbolAddress((void**)&vtp, g_vt);
    cudaGetSymbolAddress((void**)&attp, g_att);

    cudaFuncSetAttribute(gemm_h<true>,
                         cudaFuncAttributeMaxDynamicSharedMemorySize, GEMM_SMEM);
    cudaFuncSetAttribute(gemm_h<false>,
                         cudaFuncAttributeMaxDynamicSharedMemorySize, GEMM_SMEM);
    cudaFuncSetAttribute(attn_h,
                         cudaFuncAttributeMaxDynamicSharedMemorySize, ATT_SMEM);

    // 0) fp32 -> fp16 conversions
    cvt_f2h<<<(MROWS * S_D) / 1024, 256>>>(x, xh, MROWS * S_D);
    cvt_f2h<<<(QKV_N * S_D) / 1024, 256>>>(w_in, wih, QKV_N * S_D);
    cvt_f2h<<<(S_D * S_D) / 1024, 256>>>(w_out, woh, S_D * S_D);

    // 1) qkv = x @ w_in^T + b_in   (fp16 in/out, BK=64 GEMM)
    gemm_h<true><<<dim3(QKV_N / 128, MROWS / 128), 256, GEMM_SMEM>>>(
        xh, wih, b_in, qkvp, MROWS, QKV_N, S_D);

    // 2) V transpose
    transpose_v_h<<<dim3(S_S / 32, S_DH / 32, S_B * S_H), dim3(32, 8)>>>(qkvp, vtp);

    // 3) flash attention (f16-acc S, scale-folded Q, straight ldmatrix V)
    attn_h<<<dim3(S_S / 128, S_B * S_H), 128, ATT_SMEM>>>(qkvp, vtp, attp);

    // 4) out = att @ w_out^T + b_out  (fp32 out, BK=64 GEMM)
    gemm_h<false><<<dim3(S_D / 128, MROWS / 128), 256, GEMM_SMEM>>>(
        attp, woh, b_out, outp, MROWS, S_D, S_D);
}

// round 17
// speedup vs baseline: 1.0854x; 1.0854x over previous
#include <cuda_runtime.h>
#include <cuda_fp16.h>
#include <math.h>
#include <stdint.h>
#include <string.h>

#define S_B   4
#define S_S   4096
#define S_D   512
#define S_H   8
#define S_DH  64
#define QKV_N (3 * S_D)          /* 1536 */
#define MROWS (S_B * S_S)        /* 16384 */

// Scratch (allocation-free: static device globals), all fp16
__device__ __half g_xh [(size_t)MROWS * S_D];
__device__ __half g_wih[(size_t)QKV_N * S_D];
__device__ __half g_woh[(size_t)S_D * S_D];
__device__ __half g_qkv[(size_t)MROWS * QKV_N];
__device__ __half g_vt [(size_t)S_B * S_H * S_DH * S_S];
__device__ __half g_att[(size_t)MROWS * S_D];

// ---------------------------------------------------------------------------
// helpers
// ---------------------------------------------------------------------------
__device__ __forceinline__ uint32_t h2_as_u32(__half2 h)
{
    uint32_t u;
    memcpy(&u, &h, 4);
    return u;
}
__device__ __forceinline__ __half2 u32_as_h2(uint32_t u)
{
    __half2 h;
    memcpy(&h, &u, 4);
    return h;
}
__device__ __forceinline__ uint32_t ex2_h2(uint32_t x)
{
    uint32_t r;
    asm("ex2.approx.f16x2 %0, %1;" : "=r"(r) : "r"(x));
    return r;
}

// ldmatrix: four 8x8 b16 matrices
__device__ __forceinline__ void ldsm_x4(uint32_t addr, uint32_t* r)
{
    asm volatile("ldmatrix.sync.aligned.m8n8.x4.shared.b16 {%0,%1,%2,%3}, [%4];"
                 : "=r"(r[0]), "=r"(r[1]), "=r"(r[2]), "=r"(r[3]) : "r"(addr));
}

// mma.m16n8k16 fp16 (fp32 accumulate)
__device__ __forceinline__ void mma_f16(float* d, const uint32_t* a,
                                        uint32_t b0, uint32_t b1)
{
    asm volatile(
        "mma.sync.aligned.m16n8k16.row.col.f32.f16.f16.f32 "
        "{%0,%1,%2,%3}, {%4,%5,%6,%7}, {%8,%9}, {%0,%1,%2,%3};\n"
        : "+f"(d[0]), "+f"(d[1]), "+f"(d[2]), "+f"(d[3])
        : "r"(a[0]), "r"(a[1]), "r"(a[2]), "r"(a[3]), "r"(b0), "r"(b1));
}

__device__ __forceinline__ void cp_async16(uint32_t saddr, const void* gptr)
{
    asm volatile("cp.async.cg.shared.global [%0], [%1], 16;\n"
                 :: "r"(saddr), "l"(gptr));
}

// ---------------------------------------------------------------------------
// fp32 -> fp16 conversion (n multiple of 4)
// ---------------------------------------------------------------------------
__global__ __launch_bounds__(256) void cvt_f2h(
    const float* __restrict__ in, __half* __restrict__ out, int n)
{
    int i = (blockIdx.x * 256 + threadIdx.x) * 4;
    if (i < n) {
        float4 v = *(const float4*)(in + i);
        *(__half2*)(out + i)     = __floats2half2_rn(v.x, v.y);
        *(__half2*)(out + i + 2) = __floats2half2_rn(v.z, v.w);
    }
}

// ---------------------------------------------------------------------------
// fp16 GEMM:  C[M,N] = A[M,K] @ B[N,K]^T + bias[N]
// 128x128 tile, 256 threads, 3-stage cp.async ring, single barrier/chunk,
// BK=64. (unchanged measured-best)
// ---------------------------------------------------------------------------
#define GLD 72                                      /* smem stride in halves */
#define GSTG 3
#define GSTAGE_H (128 * GLD)                        /* per-operand stage, halves */
#define GEMM_SMEM (GSTG * 2 * GSTAGE_H * 2)         /* 110592 bytes */

template<bool OUT_HALF>
__global__ __launch_bounds__(256, 2) void gemm_h(
    const __half* __restrict__ A, const __half* __restrict__ Bw,
    const float* __restrict__ bias, void* __restrict__ Cout,
    int M, int N, int K)
{
    extern __shared__ char smraw[];
    __half* As = (__half*)smraw;                 // [3][128*GLD]
    __half* Bs = As + GSTG * GSTAGE_H;

    const int t    = threadIdx.x;
    const int warp = t >> 5;
    const int lane = t & 31;
    const int g    = lane >> 2;
    const int tg   = lane & 3;
    const int wm   = (warp >> 1) * 32;
    const int wn   = (warp & 1) * 64;

    const int a_row = lane & 15;
    const int a_col = (lane >> 4) * 8;
    const int b_row = (lane & 7) + ((lane >> 4) << 3);
    const int b_col = ((lane >> 3) & 1) * 8;

    const int m0 = blockIdx.y * 128;
    const int n0 = blockIdx.x * 128;

    uint32_t sA = (uint32_t)__cvta_generic_to_shared(As);
    uint32_t sB = (uint32_t)__cvta_generic_to_shared(Bs);

    // staging: 1024 16B-units per operand per chunk; 4 units/thread
    uint32_t soff[4];
    size_t   goffA[4], goffB[4];
    #pragma unroll
    for (int i = 0; i < 4; i++) {
        int u   = t + i * 256;
        int row = u >> 3;
        int seg = u & 7;
        soff[i]  = (uint32_t)(row * GLD + seg * 8) * 2;
        goffA[i] = (size_t)(m0 + row) * K + seg * 8;
        goffB[i] = (size_t)(n0 + row) * K + seg * 8;
    }

    const int nk = K / 64;

    auto issue = [&](int k, int s) {
        uint32_t off = (uint32_t)(s * GSTAGE_H) * 2;
        #pragma unroll
        for (int i = 0; i < 4; i++) {
            cp_async16(sA + off + soff[i], A  + goffA[i] + k * 64);
            cp_async16(sB + off + soff[i], Bw + goffB[i] + k * 64);
        }
        asm volatile("cp.async.commit_group;\n");
    };

    issue(0, 0);
    issue(1, 1);

    float acc[2][8][4];
    #pragma unroll
    for (int mf = 0; mf < 2; mf++)
        #pragma unroll
        for (int nf = 0; nf < 8; nf++)
            #pragma unroll
            for (int c = 0; c < 4; c++) acc[mf][nf][c] = 0.f;

    int s_cur = 0;
    int s_pre = 2;

    for (int kc = 0; kc < nk; kc++) {
        if (kc + 1 < nk) {
            asm volatile("cp.async.wait_group 1;\n");
        } else {
            asm volatile("cp.async.wait_group 0;\n");
        }
        __syncthreads();   // data ready + stage s_pre provably drained

        if (kc + 2 < nk)
            issue(kc + 2, s_pre);

        const uint32_t aA = sA + (uint32_t)(s_cur * GSTAGE_H) * 2;
        const uint32_t aB = sB + (uint32_t)(s_cur * GSTAGE_H) * 2;

        #pragma unroll
        for (int kf = 0; kf < 4; kf++) {
            const int kk0 = kf * 16;

            uint32_t af[2][4];
            #pragma unroll
            for (int mf = 0; mf < 2; mf++)
                ldsm_x4(aA + (uint32_t)((wm + mf * 16 + a_row) * GLD + kk0 + a_col) * 2,
                        af[mf]);

            #pragma unroll
            for (int np = 0; np < 4; np++) {
                uint32_t bf[4];
                ldsm_x4(aB + (uint32_t)((wn + np * 16 + b_row) * GLD + kk0 + b_col) * 2,
                        bf);
                mma_f16(acc[0][2 * np],     af[0], bf[0], bf[1]);
                mma_f16(acc[1][2 * np],     af[1], bf[0], bf[1]);
                mma_f16(acc[0][2 * np + 1], af[0], bf[2], bf[3]);
                mma_f16(acc[1][2 * np + 1], af[1], bf[2], bf[3]);
            }
        }

        s_cur = (s_cur == 2) ? 0 : s_cur + 1;
        s_pre = (s_pre == 2) ? 0 : s_pre + 1;
    }

    #pragma unroll
    for (int nf = 0; nf < 8; nf++) {
        int col = n0 + wn + nf * 8 + 2 * tg;
        float2 bb = *(const float2*)(bias + col);
        #pragma unroll
        for (int mf = 0; mf < 2; mf++) {
            int row = m0 + wm + mf * 16 + g;
            if (OUT_HALF) {
                __half* C = (__half*)Cout;
                *(__half2*)(C + (size_t)row * N + col) =
                    __floats2half2_rn(acc[mf][nf][0] + bb.x, acc[mf][nf][1] + bb.y);
                *(__half2*)(C + (size_t)(row + 8) * N + col) =
                    __floats2half2_rn(acc[mf][nf][2] + bb.x, acc[mf][nf][3] + bb.y);
            } else {
                float* C = (float*)Cout;
                *(float2*)(C + (size_t)row * N + col) =
                    make_float2(acc[mf][nf][0] + bb.x, acc[mf][nf][1] + bb.y);
                *(float2*)(C + (size_t)(row + 8) * N + col) =
                    make_float2(acc[mf][nf][2] + bb.x, acc[mf][nf][3] + bb.y);
            }
        }
    }
}

// ---------------------------------------------------------------------------
// V transpose (fp16): qkv V section [b][s][h*64+d] -> g_vt [bh][d][s]
// ---------------------------------------------------------------------------
__global__ __launch_bounds__(256) void transpose_v_h(
    const __half* __restrict__ qkv, __half* __restrict__ vt)
{
    __shared__ __half tile[32][34];
    const int bh = blockIdx.z;
    const int b  = bh >> 3;
    const int h  = bh & 7;
    const int d0 = blockIdx.y * 32;
    const int s0 = blockIdx.x * 32;
    const int tx = threadIdx.x;
    const int ty = threadIdx.y;

    const __half* src = qkv + (size_t)(b * S_S) * QKV_N + 2 * S_D + h * S_DH;
    #pragma unroll
    for (int i = 0; i < 4; i++)
        tile[ty + i * 8][tx] = src[(size_t)(s0 + ty + i * 8) * QKV_N + d0 + tx];
    __syncthreads();

    __half* dst = vt + (size_t)bh * S_DH * S_S;
    #pragma unroll
    for (int i = 0; i < 4; i++)
        dst[(size_t)(d0 + ty + i * 8) * S_S + s0 + tx] = tile[tx][ty + i * 8];
}

// ---------------------------------------------------------------------------
// Flash attention (R14 measured-best form + scale folded into Q):
// fp16 mma, fp32 S accumulate, pack->ex2.f16x2 softmax (NO per-chunk scale
// mul — 0.125*log2e folded into Q at staging), pre-transposed V, straight
// ldmatrix, cp.async double-buffered K/V, single barrier per tile.
// ---------------------------------------------------------------------------
#define LDQ  72
#define LDKs 72
#define LDVt 136
#define K_STAGE_H (128 * LDKs)            /* 9216 halves */
#define V_STAGE_H (64 * LDVt)             /* 8704 halves */
#define STAGE_H   (K_STAGE_H + V_STAGE_H) /* 17920 halves = 35840 B */
#define ATT_SMEM  (2 * STAGE_H * 2)       /* 71680 B */

__device__ __forceinline__ void attn_issue_stage(
    uint32_t sbase, int stage, const __half* kb, const __half* vb,
    int kt, int t)
{
    uint32_t kdst = sbase + (uint32_t)(stage * STAGE_H) * 2;
    uint32_t vdst = kdst + (uint32_t)K_STAGE_H * 2;
    #pragma unroll
    for (int u = t; u < 1024; u += 128) {          // K: 128 keys x 64 dims
        int row = u >> 3, sg = u & 7;
        cp_async16(kdst + (uint32_t)(row * LDKs + sg * 8) * 2,
                   kb + (size_t)(kt + row) * QKV_N + sg * 8);
    }
    #pragma unroll
    for (int u = t; u < 1024; u += 128) {          // V^T: 64 dims x 128 keys
        int d = u >> 4, sg = u & 15;
        cp_async16(vdst + (uint32_t)(d * LDVt + sg * 8) * 2,
                   vb + (size_t)d * S_S + kt + sg * 8);
    }
}

__global__ __launch_bounds__(128) void attn_h(
    const __half* __restrict__ qkv, const __half* __restrict__ vt,
    __half* __restrict__ att)
{
    extern __shared__ char smraw[];
    __half* sm = (__half*)smraw;
    const uint32_t sbase = (uint32_t)__cvta_generic_to_shared(sm);

    const int t    = threadIdx.x;
    const int warp = t >> 5;
    const int lane = t & 31;
    const int g    = lane >> 2;
    const int tg   = lane & 3;

    const int a_row = lane & 15;
    const int a_col = (lane >> 4) * 8;
    const int b_row = (lane & 7) + ((lane >> 4) << 3);
    const int b_col = ((lane >> 3) & 1) * 8;

    const int bh = blockIdx.y;
    const int b  = bh >> 3;
    const int h  = bh & 7;
    const int q0 = blockIdx.x * 128;

    const __half* kb = qkv + (size_t)b * S_S * QKV_N + S_D + h * S_DH;
    const __half* vb = vt + (size_t)bh * S_DH * S_S;

    // ---- prologue: prefetch tile 0 into stage 0 ----
    attn_issue_stage(sbase, 0, kb, vb, 0, t);
    asm volatile("cp.async.commit_group;\n");

    // 0.125 (1/sqrt(dh)) * log2(e): fold into Q so exp(sS) = 2^(QK)
    const __half2 SCQ = __floats2half2_rn(0.18033688f, 0.18033688f);

    // ---- stage Q (pre-scaled) into stage-1 K region (9216 halves) ----
    __half* Qs = sm + STAGE_H;
    const uint32_t qaddr = sbase + (uint32_t)STAGE_H * 2;
    const __half* qb = qkv + (size_t)(b * S_S + q0) * QKV_N + h * S_DH;
    #pragma unroll
    for (int u = t; u < 1024; u += 128) {
        int row = u >> 3, sg = u & 7;
        float4 raw = *(const float4*)(qb + (size_t)row * QKV_N + sg * 8);
        __half2* p = (__half2*)&raw;
        p[0] = __hmul2(p[0], SCQ);
        p[1] = __hmul2(p[1], SCQ);
        p[2] = __hmul2(p[2], SCQ);
        p[3] = __hmul2(p[3], SCQ);
        *(float4*)(Qs + row * LDQ + sg * 8) = raw;
    }
    __syncthreads();

    // ---- Q A-fragments via ldmatrix, held for the whole KV loop ----
    uint32_t qa[4][2][4];
    #pragma unroll
    for (int kf = 0; kf < 4; kf++)
        #pragma unroll
        for (int mf = 0; mf < 2; mf++)
            ldsm_x4(qaddr + (uint32_t)((warp * 32 + mf * 16 + a_row) * LDQ
                                       + kf * 16 + a_col) * 2,
                    qa[kf][mf]);
    __syncthreads();   // all warps done reading Q before stage 1 is overwritten

    float of[8][2][4];
    #pragma unroll
    for (int nf = 0; nf < 8; nf++)
        #pragma unroll
        for (int mf = 0; mf < 2; mf++)
            #pragma unroll
            for (int c = 0; c < 4; c++) of[nf][mf][c] = 0.f;

    float lsl[2] = {0.f, 0.f};
    float lsh[2] = {0.f, 0.f};

    const int NT = S_S / 128;    // 32 tiles

    for (int it = 0; it < NT; it++) {
        asm volatile("cp.async.wait_group 0;\n");
        __syncthreads();   // data ready + opposite stage provably drained

        if (it + 1 < NT) {
            attn_issue_stage(sbase, (it + 1) & 1, kb, vb, (it + 1) * 128, t);
            asm volatile("cp.async.commit_group;\n");
        }

        const uint32_t kaddr = sbase + (uint32_t)((it & 1) * STAGE_H) * 2;
        const uint32_t vaddr = kaddr + (uint32_t)K_STAGE_H * 2;

        #pragma unroll
        for (int c = 0; c < 8; c++) {            // 8 chunks of 16 keys
            // ---- S chunk (fp32 acc): rows 32 x keys 16 ----
            float sf[2][2][4];
            #pragma unroll
            for (int nf = 0; nf < 2; nf++)
                #pragma unroll
                for (int mf = 0; mf < 2; mf++)
                    #pragma unroll
                    for (int cc = 0; cc < 4; cc++) sf[nf][mf][cc] = 0.f;

            #pragma unroll
            for (int kf = 0; kf < 4; kf++) {
                uint32_t kb4[4];
                ldsm_x4(kaddr + (uint32_t)((16 * c + b_row) * LDKs
                                           + kf * 16 + b_col) * 2, kb4);
                mma_f16(sf[0][0], qa[kf][0], kb4[0], kb4[1]);
                mma_f16(sf[0][1], qa[kf][1], kb4[0], kb4[1]);
                mma_f16(sf[1][0], qa[kf][0], kb4[2], kb4[3]);
                mma_f16(sf[1][1], qa[kf][1], kb4[2], kb4[3]);
            }

            // ---- softmax: pack -> ex2.f16x2 (scale already in Q) ----
            uint32_t pa[2][4];
            #pragma unroll
            for (int mf = 0; mf < 2; mf++) {
                uint32_t p0 = h2_as_u32(__floats2half2_rn(sf[0][mf][0], sf[0][mf][1]));
                uint32_t p1 = h2_as_u32(__floats2half2_rn(sf[0][mf][2], sf[0][mf][3]));
                uint32_t p2 = h2_as_u32(__floats2half2_rn(sf[1][mf][0], sf[1][mf][1]));
                uint32_t p3 = h2_as_u32(__floats2half2_rn(sf[1][mf][2], sf[1][mf][3]));
                uint32_t e0 = ex2_h2(p0);
                uint32_t e1 = ex2_h2(p1);
                uint32_t e2 = ex2_h2(p2);
                uint32_t e3 = ex2_h2(p3);
                __half2 sl = __hadd2(u32_as_h2(e0), u32_as_h2(e2));
                __half2 sh = __hadd2(u32_as_h2(e1), u32_as_h2(e3));
                lsl[mf] += __low2float(sl) + __high2float(sl);
                lsh[mf] += __low2float(sh) + __high2float(sh);
                pa[mf][0] = e0;
                pa[mf][1] = e1;
                pa[mf][2] = e2;
                pa[mf][3] = e3;
            }

            // ---- O += P @ V (keys 16c..16c+15) ----
            #pragma unroll
            for (int np = 0; np < 4; np++) {
                uint32_t v4[4];
                ldsm_x4(vaddr + (uint32_t)((np * 16 + b_row) * LDVt
                                           + 16 * c + b_col) * 2, v4);
                mma_f16(of[2 * np][0],     pa[0], v4[0], v4[1]);
                mma_f16(of[2 * np][1],     pa[1], v4[0], v4[1]);
                mma_f16(of[2 * np + 1][0], pa[0], v4[2], v4[3]);
                mma_f16(of[2 * np + 1][1], pa[1], v4[2], v4[3]);
            }
        }
        // no trailing __syncthreads: next iteration's barrier protects reuse
    }

    // ---- epilogue ----
    #pragma unroll
    for (int mf = 0; mf < 2; mf++) {
        float a = lsl[mf], bsum = lsh[mf];
        a += __shfl_xor_sync(0xffffffffu, a, 1);
        a += __shfl_xor_sync(0xffffffffu, a, 2);
        bsum += __shfl_xor_sync(0xffffffffu, bsum, 1);
        bsum += __shfl_xor_sync(0xffffffffu, bsum, 2);
        float il = 1.f / a;
        float ih = 1.f / bsum;

        int row = q0 + warp * 32 + mf * 16 + g;
        __half* o0 = att + (size_t)(b * S_S + row) * S_D + h * S_DH;
        __half* o1 = o0 + 8 * S_D;
        #pragma unroll
        for (int nf = 0; nf < 8; nf++) {
            int col = nf * 8 + 2 * tg;
            *(__half2*)(o0 + col) =
                __floats2half2_rn(of[nf][mf][0] * il, of[nf][mf][1] * il);
            *(__half2*)(o1 + col) =
                __floats2half2_rn(of[nf][mf][2] * ih, of[nf][mf][3] * ih);
        }
    }
}

// ---------------------------------------------------------------------------
extern "C" void kernel_launch(void* const* d_in, const int* in_sizes, int n_in,
                              void* d_out, int out_size)
{
    (void)in_sizes; (void)n_in; (void)out_size;
    const float* x     = (const float*)d_in[0];
    const float* w_in  = (const float*)d_in[1];
    const float* b_in  = (const float*)d_in[2];
    const float* w_out = (const float*)d_in[3];
    const float* b_out = (const float*)d_in[4];
    float* outp = (float*)d_out;

    __half *xh, *wih, *woh, *qkvp, *vtp, *attp;
    cudaGetSymbolAddress((void**)&xh,  g_xh);
    cudaGetSymbolAddress((void**)&wih, g_wih);
    cudaGetSymbolAddress((void**)&woh, g_woh);
    cudaGetSymbolAddress((void**)&qkvp, g_qkv);
    cudaGetSymbolAddress((void**)&vtp, g_vt);
    cudaGetSymbolAddress((void**)&attp, g_att);

    cudaFuncSetAttribute(gemm_h<true>,
                         cudaFuncAttributeMaxDynamicSharedMemorySize, GEMM_SMEM);
    cudaFuncSetAttribute(gemm_h<false>,
                         cudaFuncAttributeMaxDynamicSharedMemorySize, GEMM_SMEM);
    cudaFuncSetAttribute(attn_h,
                         cudaFuncAttributeMaxDynamicSharedMemorySize, ATT_SMEM);

    // 0) fp32 -> fp16 conversions
    cvt_f2h<<<(MROWS * S_D) / 1024, 256>>>(x, xh, MROWS * S_D);
    cvt_f2h<<<(QKV_N * S_D) / 1024, 256>>>(w_in, wih, QKV_N * S_D);
    cvt_f2h<<<(S_D * S_D) / 1024, 256>>>(w_out, woh, S_D * S_D);

    // 1) qkv = x @ w_in^T + b_in   (fp16 in/out, BK=64 GEMM)
    gemm_h<true><<<dim3(QKV_N / 128, MROWS / 128), 256, GEMM_SMEM>>>(
        xh, wih, b_in, qkvp, MROWS, QKV_N, S_D);

    // 2) V transpose
    transpose_v_h<<<dim3(S_S / 32, S_DH / 32, S_B * S_H), dim3(32, 8)>>>(qkvp, vtp);

    // 3) flash attention (R14 form, scale folded into Q)
    attn_h<<<dim3(S_S / 128, S_B * S_H), 128, ATT_SMEM>>>(qkvp, vtp, attp);

    // 4) out = att @ w_out^T + b_out  (fp32 out, BK=64 GEMM)
    gemm_h<false><<<dim3(S_D / 128, MROWS / 128), 256, GEMM_SMEM>>>(
        attp, woh, b_out, outp, MROWS, S_D, S_D);
}